// round 12
// baseline (speedup 1.0000x reference)
#include <cuda_runtime.h>
#include <cuda_bf16.h>
#include <cstdint>

#define B_DIM   2048
#define IN_DIM  16384
#define OUT_DIM 16384

// ---------------- global scratch (static, no runtime alloc) ----------------
__device__ uint16_t g_xqT[(size_t)IN_DIM * B_DIM];   // transposed u16-quantized x (64MB)
__device__ uint32_t g_idxpack[OUT_DIM];              // ia | (ib<<16)
__device__ float4   g_coef[OUT_DIM];                 // (c0, ca*2^-16, cb*2^-16, cab*2^-32)

__device__ __forceinline__ uint32_t quant16(float v) {
    return (uint32_t)fminf(fmaf(v, 65536.0f, 0.5f), 65535.0f);
}

// ---------------- fused kernel: transpose tiles + prep tail blocks ----------------
#define TP_BLOCKS ((IN_DIM / 64) * (B_DIM / 64))     // 8192
#define PREP_BLOCKS (OUT_DIM / 256)                  // 64
#define TS32 33                                      // u32 tile stride

__global__ __launch_bounds__(256)
void mid_kernel(const float* __restrict__ x,
                const float* __restrict__ w,
                const int* __restrict__ idx_a,
                const int* __restrict__ idx_b) {
    __shared__ uint32_t tile32[64 * TS32];           // 8448 B
    const int t = threadIdx.x;

    if (blockIdx.x >= TP_BLOCKS) {
        // ---- prep path ----
        int n = (blockIdx.x - TP_BLOCKS) * 256 + t;
        float p[16];
        const float4* wp = reinterpret_cast<const float4*>(w + (size_t)n * 16);
        float4 w0 = wp[0], w1 = wp[1], w2 = wp[2], w3 = wp[3];
        p[0]=w0.x; p[1]=w0.y; p[2]=w0.z; p[3]=w0.w;
        p[4]=w1.x; p[5]=w1.y; p[6]=w1.z; p[7]=w1.w;
        p[8]=w2.x; p[9]=w2.y; p[10]=w2.z; p[11]=w2.w;
        p[12]=w3.x; p[13]=w3.y; p[14]=w3.z; p[15]=w3.w;

        float m = p[0];
        #pragma unroll
        for (int i = 1; i < 16; i++) m = fmaxf(m, p[i]);
        float s = 0.f;
        #pragma unroll
        for (int i = 0; i < 16; i++) { p[i] = expf(p[i] - m); s += p[i]; }
        float inv = 1.0f / s;
        #pragma unroll
        for (int i = 0; i < 16; i++) p[i] *= inv;

        // gates = c0 + ca*a + cb*b + cab*ab
        float c0  = p[8]+p[9]+p[10]+p[11]+p[12]+p[13]+p[14]+p[15];
        float ca  = p[2]+p[3]+p[6]+p[7] - p[8]-p[9]-p[12]-p[13];
        float cb  = p[4]+p[5]+p[6]+p[7] - p[8]-p[9]-p[10]-p[11];
        float cab = p[1] - p[2] - p[4] - 2.0f*p[6] - p[7]
                  + p[8] + 2.0f*p[9] + p[11] + p[13] - p[14];

        g_idxpack[n] = (uint32_t)idx_a[n] | ((uint32_t)idx_b[n] << 16);
        const float S1 = 1.52587890625e-05f;        // 2^-16
        const float S2 = 2.3283064365386963e-10f;   // 2^-32
        g_coef[n] = make_float4(c0, ca * S1, cb * S1, cab * S2);
        return;
    }

    // ---- transpose path ----
    const int i0 = (blockIdx.x % (IN_DIM / 64)) * 64;
    const int b0 = (blockIdx.x / (IN_DIM / 64)) * 64;

    // Read: batch all 4 float4-pairs first (MLP), then quantize+scatter.
    {
        const int c = t & 15;            // i-quad
        const int r = t >> 4;            // b-pair base 0..15
        float4 v0[2], v1[2];
        #pragma unroll
        for (int rr = 0; rr < 2; rr++) {
            int bp = r + 16 * rr;
            v0[rr] = __ldcs(reinterpret_cast<const float4*>(
                x + (size_t)(b0 + 2*bp    ) * IN_DIM + i0 + 4*c));
            v1[rr] = __ldcs(reinterpret_cast<const float4*>(
                x + (size_t)(b0 + 2*bp + 1) * IN_DIM + i0 + 4*c));
        }
        #pragma unroll
        for (int rr = 0; rr < 2; rr++) {
            int bp = r + 16 * rr;
            tile32[(4*c + 0) * TS32 + bp] = quant16(v0[rr].x) | (quant16(v1[rr].x) << 16);
            tile32[(4*c + 1) * TS32 + bp] = quant16(v0[rr].y) | (quant16(v1[rr].y) << 16);
            tile32[(4*c + 2) * TS32 + bp] = quant16(v0[rr].z) | (quant16(v1[rr].z) << 16);
            tile32[(4*c + 3) * TS32 + bp] = quant16(v0[rr].w) | (quant16(v1[rr].w) << 16);
        }
    }
    __syncthreads();

    // Write: coalesced uint2 stores; skip L1 (write-once, read later from L2).
    {
        const int m  = t & 15;
        const int ir = t >> 4;
        #pragma unroll
        for (int ii = 0; ii < 4; ii++) {
            int il = ir + 16 * ii;
            uint2 q;
            q.x = tile32[il * TS32 + 2*m];
            q.y = tile32[il * TS32 + 2*m + 1];
            __stcg(reinterpret_cast<uint2*>(&g_xqT[(size_t)(i0 + il) * B_DIM + b0 + 4*m]), q);
        }
    }
}

// ---------------- main evaluation ----------------
// CTA tile: NT=64 outputs x BT=128 batch. 512 threads, 16 warps, 4 outputs/warp.
#define NT 64
#define BT 128
#define TSO 130                          // fp32 tile row stride
__global__ __launch_bounds__(512, 2)
void main_kernel(float* __restrict__ out) {
    __shared__ float tileo[NT * TSO];    // 33280 B
    const int t   = threadIdx.x;
    const int l   = t & 31;
    const int wpi = t >> 5;
    const int n0  = blockIdx.x * NT;
    const int b0  = blockIdx.y * BT;

    // ---- metadata first (L1-hittable), then ALL operand loads (MLP=16) ----
    uint32_t ip[4];
    float4   c[4];
    #pragma unroll
    for (int q = 0; q < 4; q++) {
        const int n = n0 + wpi * 4 + q;
        ip[q] = __ldg(&g_idxpack[n]);
        c[q]  = __ldg(&g_coef[n]);
    }

    uint32_t Aw[4][2], Bw[4][2];
    #pragma unroll
    for (int q = 0; q < 4; q++) {
        const uint32_t* ra = reinterpret_cast<const uint32_t*>(
            g_xqT + (size_t)(ip[q] & 0xFFFFu) * B_DIM + b0);
        const uint32_t* rb = reinterpret_cast<const uint32_t*>(
            g_xqT + (size_t)(ip[q] >> 16) * B_DIM + b0);
        #pragma unroll
        for (int h = 0; h < 2; h++) {
            Aw[q][h] = __ldcg(ra + l + 32 * h);   // bypass L1: never resident
            Bw[q][h] = __ldcg(rb + l + 32 * h);
        }
    }

    // ---- compute + stage into smem tile ----
    #pragma unroll
    for (int q = 0; q < 4; q++) {
        const int nl = wpi * 4 + q;
        #pragma unroll
        for (int h = 0; h < 2; h++) {
            int wd = l + 32 * h;
            uint32_t A = Aw[q][h], B = Bw[q][h];
            float fa0 = (float)(A & 0xFFFFu), fa1 = (float)(A >> 16);
            float fb0 = (float)(B & 0xFFFFu), fb1 = (float)(B >> 16);
            float v0 = fmaf(c[q].y, fa0, c[q].x); v0 = fmaf(c[q].z, fb0, v0); v0 = fmaf(c[q].w, fa0*fb0, v0);
            float v1 = fmaf(c[q].y, fa1, c[q].x); v1 = fmaf(c[q].z, fb1, v1); v1 = fmaf(c[q].w, fa1*fb1, v1);
            *reinterpret_cast<float2*>(&tileo[nl * TSO + 2 * wd]) = make_float2(v0, v1);
        }
    }
    __syncthreads();

    // ---- coalesced streaming write-out ----
    {
        const int nl = t & (NT - 1);
        const int bb = t >> 6;           // 0..7
        #pragma unroll
        for (int j2 = 0; j2 < BT / 8; j2++) {
            int bl = bb + 8 * j2;
            float v = tileo[nl * TSO + bl];
            __stcs(out + (size_t)(b0 + bl) * OUT_DIM + n0 + nl, v);
        }
    }
}

extern "C" void kernel_launch(void* const* d_in, const int* in_sizes, int n_in,
                              void* d_out, int out_size) {
    const float* x   = (const float*)d_in[0];
    const float* w   = (const float*)d_in[1];
    const int*   ia  = (const int*)d_in[2];
    const int*   ib  = (const int*)d_in[3];
    float* out = (float*)d_out;

    mid_kernel<<<TP_BLOCKS + PREP_BLOCKS, 256>>>(x, w, ia, ib);

    dim3 mg(OUT_DIM / NT, B_DIM / BT);   // 256 x 16
    main_kernel<<<mg, 512>>>(out);
}

// round 15
// speedup vs baseline: 1.1190x; 1.1190x over previous
#include <cuda_runtime.h>
#include <cuda_bf16.h>
#include <cstdint>

#define B_DIM   2048
#define IN_DIM  16384
#define OUT_DIM 16384

// ---------------- global scratch (static, no runtime alloc) ----------------
__device__ uint16_t g_xqT[(size_t)IN_DIM * B_DIM];   // transposed u16-quantized x (64MB)
__device__ uint32_t g_idxpack[OUT_DIM];              // ia | (ib<<16)
__device__ float4   g_coef[OUT_DIM];                 // (c0, ca*2^-16, cb*2^-16, cab*2^-32)

__device__ __forceinline__ uint32_t quant16(float v) {
    return (uint32_t)fminf(fmaf(v, 65536.0f, 0.5f), 65535.0f);
}

// u16 halves of a u32 word -> exact floats, no I2F: PRMT + FADD (full-rate pipes).
__device__ __forceinline__ float code_lo(uint32_t w) {
    return __uint_as_float(__byte_perm(w, 0x4B00, 0x5410)) - 8388608.0f;
}
__device__ __forceinline__ float code_hi(uint32_t w) {
    return __uint_as_float(__byte_perm(w, 0x4B00, 0x5432)) - 8388608.0f;
}

// ---------------- fused kernel: transpose tiles + prep tail blocks ----------------
#define TP_BLOCKS ((IN_DIM / 64) * (B_DIM / 64))     // 8192
#define PREP_BLOCKS (OUT_DIM / 256)                  // 64
#define TS32 33                                      // u32 tile stride

__global__ __launch_bounds__(256)
void mid_kernel(const float* __restrict__ x,
                const float* __restrict__ w,
                const int* __restrict__ idx_a,
                const int* __restrict__ idx_b) {
    __shared__ uint32_t tile32[64 * TS32];           // 8448 B
    const int t = threadIdx.x;

    if (blockIdx.x >= TP_BLOCKS) {
        // ---- prep path ----
        int n = (blockIdx.x - TP_BLOCKS) * 256 + t;
        float p[16];
        const float4* wp = reinterpret_cast<const float4*>(w + (size_t)n * 16);
        float4 w0 = wp[0], w1 = wp[1], w2 = wp[2], w3 = wp[3];
        p[0]=w0.x; p[1]=w0.y; p[2]=w0.z; p[3]=w0.w;
        p[4]=w1.x; p[5]=w1.y; p[6]=w1.z; p[7]=w1.w;
        p[8]=w2.x; p[9]=w2.y; p[10]=w2.z; p[11]=w2.w;
        p[12]=w3.x; p[13]=w3.y; p[14]=w3.z; p[15]=w3.w;

        float m = p[0];
        #pragma unroll
        for (int i = 1; i < 16; i++) m = fmaxf(m, p[i]);
        float s = 0.f;
        #pragma unroll
        for (int i = 0; i < 16; i++) { p[i] = expf(p[i] - m); s += p[i]; }
        float inv = 1.0f / s;
        #pragma unroll
        for (int i = 0; i < 16; i++) p[i] *= inv;

        // gates = c0 + ca*a + cb*b + cab*ab
        float c0  = p[8]+p[9]+p[10]+p[11]+p[12]+p[13]+p[14]+p[15];
        float ca  = p[2]+p[3]+p[6]+p[7] - p[8]-p[9]-p[12]-p[13];
        float cb  = p[4]+p[5]+p[6]+p[7] - p[8]-p[9]-p[10]-p[11];
        float cab = p[1] - p[2] - p[4] - 2.0f*p[6] - p[7]
                  + p[8] + 2.0f*p[9] + p[11] + p[13] - p[14];

        g_idxpack[n] = (uint32_t)idx_a[n] | ((uint32_t)idx_b[n] << 16);
        const float S1 = 1.52587890625e-05f;        // 2^-16
        const float S2 = 2.3283064365386963e-10f;   // 2^-32
        g_coef[n] = make_float4(c0, ca * S1, cb * S1, cab * S2);
        return;
    }

    // ---- transpose path ----
    const int i0 = (blockIdx.x % (IN_DIM / 64)) * 64;
    const int b0 = (blockIdx.x / (IN_DIM / 64)) * 64;

    {
        const int c = t & 15;            // i-quad
        const int r = t >> 4;            // b-pair base 0..15
        float4 v0[2], v1[2];
        #pragma unroll
        for (int rr = 0; rr < 2; rr++) {
            int bp = r + 16 * rr;
            v0[rr] = __ldcs(reinterpret_cast<const float4*>(
                x + (size_t)(b0 + 2*bp    ) * IN_DIM + i0 + 4*c));
            v1[rr] = __ldcs(reinterpret_cast<const float4*>(
                x + (size_t)(b0 + 2*bp + 1) * IN_DIM + i0 + 4*c));
        }
        #pragma unroll
        for (int rr = 0; rr < 2; rr++) {
            int bp = r + 16 * rr;
            tile32[(4*c + 0) * TS32 + bp] = quant16(v0[rr].x) | (quant16(v1[rr].x) << 16);
            tile32[(4*c + 1) * TS32 + bp] = quant16(v0[rr].y) | (quant16(v1[rr].y) << 16);
            tile32[(4*c + 2) * TS32 + bp] = quant16(v0[rr].z) | (quant16(v1[rr].z) << 16);
            tile32[(4*c + 3) * TS32 + bp] = quant16(v0[rr].w) | (quant16(v1[rr].w) << 16);
        }
    }
    __syncthreads();

    {
        const int m  = t & 15;
        const int ir = t >> 4;
        #pragma unroll
        for (int ii = 0; ii < 4; ii++) {
            int il = ir + 16 * ii;
            uint2 q;
            q.x = tile32[il * TS32 + 2*m];
            q.y = tile32[il * TS32 + 2*m + 1];
            __stcg(reinterpret_cast<uint2*>(&g_xqT[(size_t)(i0 + il) * B_DIM + b0 + 4*m]), q);
        }
    }
}

// ---------------- main evaluation ----------------
// CTA tile: NT=64 outputs x BT=128 batch. 512 threads, 16 warps, 4 outputs/warp.
// Round-10 structure (regs<=32, 4 CTAs/SM) + PRMT/FADD decode + 3-FMA eval.
#define NT 64
#define BT 128
#define TSO 130                          // fp32 tile row stride
__global__ __launch_bounds__(512, 4)
void main_kernel(float* __restrict__ out) {
    __shared__ float tileo[NT * TSO];    // 33280 B
    const int t   = threadIdx.x;
    const int l   = t & 31;
    const int wpi = t >> 5;
    const int n0  = blockIdx.x * NT;
    const int b0  = blockIdx.y * BT;

    #pragma unroll
    for (int q = 0; q < 4; q++) {
        const int nl = wpi * 4 + q;
        const int n  = n0 + nl;
        uint32_t ip = __ldg(&g_idxpack[n]);
        float4  c   = __ldg(&g_coef[n]);
        const uint32_t* ra = reinterpret_cast<const uint32_t*>(
            g_xqT + (size_t)(ip & 0xFFFFu) * B_DIM + b0);
        const uint32_t* rb = reinterpret_cast<const uint32_t*>(
            g_xqT + (size_t)(ip >> 16) * B_DIM + b0);

        #pragma unroll
        for (int h = 0; h < 2; h++) {
            int wd = l + 32 * h;
            uint32_t A = __ldcg(ra + wd);
            uint32_t B = __ldcg(rb + wd);
            float fa0 = code_lo(A), fa1 = code_hi(A);
            float fb0 = code_lo(B), fb1 = code_hi(B);
            // out = c0 + ca'*fa + cb'*fb + cab'*fa*fb, 3 FMAs:
            float v0 = fmaf(fmaf(c.w, fb0, c.y), fa0, fmaf(c.z, fb0, c.x));
            float v1 = fmaf(fmaf(c.w, fb1, c.y), fa1, fmaf(c.z, fb1, c.x));
            *reinterpret_cast<float2*>(&tileo[nl * TSO + 2 * wd]) = make_float2(v0, v1);
        }
    }
    __syncthreads();

    // Coalesced streaming write-out: warp covers 32 consecutive n.
    {
        const int nl = t & (NT - 1);
        const int bb = t >> 6;           // 0..7
        #pragma unroll
        for (int j2 = 0; j2 < BT / 8; j2++) {
            int bl = bb + 8 * j2;
            float v = tileo[nl * TSO + bl];
            __stcs(out + (size_t)(b0 + bl) * OUT_DIM + n0 + nl, v);
        }
    }
}

extern "C" void kernel_launch(void* const* d_in, const int* in_sizes, int n_in,
                              void* d_out, int out_size) {
    const float* x   = (const float*)d_in[0];
    const float* w   = (const float*)d_in[1];
    const int*   ia  = (const int*)d_in[2];
    const int*   ib  = (const int*)d_in[3];
    float* out = (float*)d_out;

    mid_kernel<<<TP_BLOCKS + PREP_BLOCKS, 256>>>(x, w, ia, ib);

    dim3 mg(OUT_DIM / NT, B_DIM / BT);   // 256 x 16
    main_kernel<<<mg, 512>>>(out);
}